// round 14
// baseline (speedup 1.0000x reference)
#include <cuda_runtime.h>
#include <cuda_fp16.h>
#include <cstdint>

// Problem constants
#define BATCH 2
#define SEQ   2048
#define DIM   1024
#define NH    16
#define HD    64
#define MROWS (BATCH*SEQ)          // 4096
#define QKV_N (3*DIM)              // 3072
#define QSC   0.18033688011112042f // 0.125 * log2(e); softmax uses ex2

// Scratch (device globals; no allocation allowed). All fp16.
__device__ __half g_xh[MROWS*DIM];        // x
__device__ __half g_wqkvth[QKV_N*DIM];    // W_qkv^T [n][k]
__device__ __half g_woutth[DIM*DIM];      // W_out^T [n][k]
__device__ __half g_qh[BATCH*NH*SEQ*HD];  // [b][h][s][d], scaled by QSC
__device__ __half g_kh[BATCH*NH*SEQ*HD];  // [b][h][s][d]
__device__ __half g_vth[BATCH*NH*HD*SEQ]; // [b][h][d][s]
__device__ __half g_aoh[BATCH*SEQ*DIM];   // attn out [b][s][h*64+d]

__device__ __forceinline__ void mma_f16(float (&d)[4],
                                        const uint32_t (&a)[4],
                                        const uint32_t (&b)[2]) {
    asm volatile(
        "mma.sync.aligned.m16n8k16.row.col.f32.f16.f16.f32 "
        "{%0,%1,%2,%3}, {%4,%5,%6,%7}, {%8,%9}, {%0,%1,%2,%3};"
        : "+f"(d[0]), "+f"(d[1]), "+f"(d[2]), "+f"(d[3])
        : "r"(a[0]), "r"(a[1]), "r"(a[2]), "r"(a[3]), "r"(b[0]), "r"(b[1]));
}

__device__ __forceinline__ void cp_async16(uint32_t smem, const void* gptr) {
    asm volatile("cp.async.cg.shared.global [%0], [%1], 16;" :: "r"(smem), "l"(gptr));
}

__device__ __forceinline__ uint32_t pack_h2(float x, float y) {
    __half2 h = __floats2half2_rn(x, y);
    return *reinterpret_cast<uint32_t*>(&h);
}

__device__ __forceinline__ float fexp2(float x) {
    float y;
    asm("ex2.approx.ftz.f32 %0, %1;" : "=f"(y) : "f"(x));
    return y;
}

__device__ __forceinline__ void ldsm_x4(uint32_t (&r)[4], uint32_t addr) {
    asm volatile(
        "ldmatrix.sync.aligned.m8n8.x4.shared.b16 {%0,%1,%2,%3}, [%4];"
        : "=r"(r[0]), "=r"(r[1]), "=r"(r[2]), "=r"(r[3]) : "r"(addr));
}

// ---------------------------------------------------------------------------
// Pre-conversion kernels (fp32 -> fp16).
// ---------------------------------------------------------------------------
__global__ void cvt_h_kernel(const float* __restrict__ src,
                             __half* __restrict__ dst, int n8) {
    int i = blockIdx.x * blockDim.x + threadIdx.x;
    if (i < n8) {
        float4 v0 = ((const float4*)src)[2 * i];
        float4 v1 = ((const float4*)src)[2 * i + 1];
        uint4 o;
        o.x = pack_h2(v0.x, v0.y);
        o.y = pack_h2(v0.z, v0.w);
        o.z = pack_h2(v1.x, v1.y);
        o.w = pack_h2(v1.z, v1.w);
        ((uint4*)dst)[i] = o;
    }
}

__global__ void cvt_t_h_kernel(const float* __restrict__ src,
                               __half* __restrict__ dst, int K, int N) {
    __shared__ float tile[32][33];
    int nb = blockIdx.x * 32, kb = blockIdx.y * 32;
    int tx = threadIdx.x, ty = threadIdx.y;
    #pragma unroll
    for (int i = 0; i < 32; i += 8)
        tile[ty + i][tx] = src[(size_t)(kb + ty + i) * N + nb + tx];
    __syncthreads();
    #pragma unroll
    for (int i = 0; i < 32; i += 8)
        dst[(size_t)(nb + ty + i) * K + kb + tx] = __float2half_rn(tile[tx][ty + i]);
}

// ---------------------------------------------------------------------------
// fp16 tensor-core GEMM: CTA 128x128, k-tile 64 halves (4 x k16 mma steps).
// 8 warps (2m x 4n). cp.async double buffer, one sync per k-tile.
// __launch_bounds__(256, 3): 3 CTAs/SM (regs capped ~85, smem 3x74KB=217KB).
// ---------------------------------------------------------------------------
#define AS_HB 144u                     // bytes per smem row (72 halves)
#define GEMM_ABUF 18432u               // 128 rows * 144 B
#define GEMM_BUFB 36864u               // A + B per stage
#define GEMM_SMEMH (2 * 36864 + 256)

__device__ __forceinline__ void gemm_tile_h(const __half* __restrict__ Abase,
                                            const __half* __restrict__ Btbase,
                                            float (&acc)[4][4][4]) {
    extern __shared__ __half smh[];
    const int K = DIM;
    const int tid = threadIdx.x;
    const int lane = tid & 31;
    const int w = tid >> 5;
    const int warpM = (w & 1) * 64;
    const int warpN = (w >> 1) * 32;

    const __half* Ag  = Abase  + (size_t)(blockIdx.y * 128) * K;
    const __half* Bgt = Btbase + (size_t)(blockIdx.x * 128) * K;

    const int sub = lane >> 3, r8 = lane & 7;
    const uint32_t lofA = (uint32_t)(((sub & 1) * 8 + r8) * AS_HB + (sub >> 1) * 16);
    const uint32_t lofB = (uint32_t)(((sub >> 1) * 8 + r8) * AS_HB + (sub & 1) * 16);
    const uint32_t smb = (uint32_t)__cvta_generic_to_shared(smh);

    const int s_row = tid >> 3;        // 0..31 (+32 per it)
    const int s_c   = tid & 7;         // 16B chunk (8 halves)

#define HSTAGE(kt, buf) { \
    uint32_t ab = smb + (uint32_t)(buf) * GEMM_BUFB; \
    uint32_t bb = ab + GEMM_ABUF; \
    _Pragma("unroll") \
    for (int it = 0; it < 4; it++) { \
        int row = s_row + it * 32; \
        cp_async16(ab + (uint32_t)(row * AS_HB + s_c * 16), \
                   Ag + (size_t)row * K + (kt) * 64 + s_c * 8); \
        cp_async16(bb + (uint32_t)(row * AS_HB + s_c * 16), \
                   Bgt + (size_t)row * K + (kt) * 64 + s_c * 8); \
    } \
    asm volatile("cp.async.commit_group;"); }

    const int NKT = K / 64;   // 16
    HSTAGE(0, 0);
    for (int kt = 0; kt < NKT; kt++) {
        asm volatile("cp.async.wait_group 0;");
        __syncthreads();
        if (kt + 1 < NKT) HSTAGE(kt + 1, (kt + 1) & 1);

        const uint32_t ab = smb + (uint32_t)(kt & 1) * GEMM_BUFB;
        const uint32_t bb = ab + GEMM_ABUF;

        #pragma unroll
        for (int ks = 0; ks < 4; ks++) {
            uint32_t af[4][4];
            #pragma unroll
            for (int mt = 0; mt < 4; mt++)
                ldsm_x4(af[mt], ab + (uint32_t)((warpM + mt * 16) * AS_HB + ks * 32) + lofA);
            uint32_t bf[4][2];
            #pragma unroll
            for (int p = 0; p < 2; p++) {
                uint32_t bq[4];
                ldsm_x4(bq, bb + (uint32_t)((warpN + p * 16) * AS_HB + ks * 32) + lofB);
                bf[2 * p][0]     = bq[0];
                bf[2 * p][1]     = bq[1];
                bf[2 * p + 1][0] = bq[2];
                bf[2 * p + 1][1] = bq[3];
            }
            #pragma unroll
            for (int mt = 0; mt < 4; mt++)
                #pragma unroll
                for (int nt = 0; nt < 4; nt++)
                    mma_f16(acc[mt][nt], af[mt], bf[nt]);
        }
    }
#undef HSTAGE
}

__global__ __launch_bounds__(256, 3) void gemm_qkv_h(const float* __restrict__ bias) {
    float acc[4][4][4];
    #pragma unroll
    for (int i = 0; i < 4; i++)
        #pragma unroll
        for (int j = 0; j < 4; j++)
            #pragma unroll
            for (int k = 0; k < 4; k++) acc[i][j][k] = 0.f;

    gemm_tile_h(g_xh, g_wqkvth, acc);

    const int tid = threadIdx.x;
    const int lane = tid & 31;
    const int w = tid >> 5;
    const int warpM = (w & 1) * 64;
    const int warpN = (w >> 1) * 32;
    const int g = lane >> 2, t = lane & 3;

    #pragma unroll
    for (int mt = 0; mt < 4; mt++) {
        #pragma unroll
        for (int nt = 0; nt < 4; nt++) {
            int col = blockIdx.x * 128 + warpN + nt * 8 + t * 2;
            float b0 = bias[col], b1 = bias[col + 1];
            int part = col >> 10;
            int h = (col >> 6) & (NH - 1);
            int d = col & (HD - 1);
            #pragma unroll
            for (int half = 0; half < 2; half++) {
                int r = blockIdx.y * 128 + warpM + mt * 16 + g + half * 8;
                int b_ = r >> 11, s = r & (SEQ - 1);
                float v0 = acc[mt][nt][half * 2 + 0] + b0;
                float v1 = acc[mt][nt][half * 2 + 1] + b1;
                if (part == 0) {
                    __half2* dst = (__half2*)(g_qh + ((size_t)(b_ * NH + h) * SEQ + s) * HD + d);
                    *dst = __floats2half2_rn(v0 * QSC, v1 * QSC);
                } else if (part == 1) {
                    __half2* dst = (__half2*)(g_kh + ((size_t)(b_ * NH + h) * SEQ + s) * HD + d);
                    *dst = __floats2half2_rn(v0, v1);
                } else {
                    size_t vb = ((size_t)(b_ * NH + h) * HD + d) * SEQ + s;
                    g_vth[vb]       = __float2half_rn(v0);
                    g_vth[vb + SEQ] = __float2half_rn(v1);
                }
            }
        }
    }
}

__global__ __launch_bounds__(256, 3) void gemm_out_h(const float* __restrict__ bias,
                                                     float* __restrict__ C) {
    float acc[4][4][4];
    #pragma unroll
    for (int i = 0; i < 4; i++)
        #pragma unroll
        for (int j = 0; j < 4; j++)
            #pragma unroll
            for (int k = 0; k < 4; k++) acc[i][j][k] = 0.f;

    gemm_tile_h(g_aoh, g_woutth, acc);

    const int tid = threadIdx.x;
    const int lane = tid & 31;
    const int w = tid >> 5;
    const int warpM = (w & 1) * 64;
    const int warpN = (w >> 1) * 32;
    const int g = lane >> 2, t = lane & 3;

    #pragma unroll
    for (int mt = 0; mt < 4; mt++) {
        #pragma unroll
        for (int nt = 0; nt < 4; nt++) {
            int col = blockIdx.x * 128 + warpN + nt * 8 + t * 2;
            float b0 = bias[col], b1 = bias[col + 1];
            #pragma unroll
            for (int half = 0; half < 2; half++) {
                int r = blockIdx.y * 128 + warpM + mt * 16 + g + half * 8;
                float2 o;
                o.x = acc[mt][nt][half * 2 + 0] + b0;
                o.y = acc[mt][nt][half * 2 + 1] + b1;
                *(float2*)(C + (size_t)r * DIM + col) = o;
            }
        }
    }
}

// ---------------------------------------------------------------------------
// fp16 causal flash attention — R11 form (single 64-kv tile per barrier).
// ---------------------------------------------------------------------------
#define QS_HB 144u
#define ATTN_QBY (128 * 144)
#define ATTN_KVB (64 * 144)
#define ATTN_BUFB (2 * ATTN_KVB)
#define ATTN_SMEMH (ATTN_QBY + 2 * ATTN_BUFB)

__global__ __launch_bounds__(256, 2) void attn_h() {
    extern __shared__ __half smh[];

    const int tid = threadIdx.x;
    const int lane = tid & 31;
    const int wp = tid >> 5;
    const int g = lane >> 2, t = lane & 3;

    const int qt = (gridDim.x - 1) - blockIdx.x;
    const int bh = blockIdx.y;
    const int q0 = qt * 128;
    const __half* Qp  = g_qh  + (size_t)bh * SEQ * HD;
    const __half* Kp  = g_kh  + (size_t)bh * SEQ * HD;
    const __half* Vtp = g_vth + (size_t)bh * HD * SEQ;

    const int sub = lane >> 3, r8 = lane & 7;
    const uint32_t lofQ = (uint32_t)(((sub & 1) * 8 + r8) * QS_HB + (sub >> 1) * 16);
    const uint32_t lofB = (uint32_t)(((sub >> 1) * 8 + r8) * QS_HB + (sub & 1) * 16);
    const uint32_t qsb  = (uint32_t)__cvta_generic_to_shared(smh);
    const uint32_t kvb0 = qsb + ATTN_QBY;

    const int st_r = tid >> 3;
    const int st_c = tid & 7;

    #define ASTG(jt, buf) { \
        uint32_t ksb = kvb0 + (uint32_t)(buf) * ATTN_BUFB; \
        uint32_t vtb = ksb + ATTN_KVB; \
        int kv0_ = (jt) * 64; \
        _Pragma("unroll") \
        for (int it = 0; it < 2; it++) { \
            int r = st_r + it * 32; \
            cp_async16(ksb + (uint32_t)(r * QS_HB + st_c * 16), \
                       Kp + (size_t)(kv0_ + r) * HD + st_c * 8); \
            cp_async16(vtb + (uint32_t)(r * QS_HB + st_c * 16), \
                       Vtp + (size_t)r * SEQ + kv0_ + st_c * 8); \
        } \
        asm volatile("cp.async.commit_group;"); }

    for (int i = tid; i < 128 * 8; i += 256) {
        int r = i >> 3, c = i & 7;
        *(uint4*)((char*)smh + r * QS_HB + c * 16) =
            *(const uint4*)(Qp + (size_t)(q0 + r) * HD + c * 8);
    }

    float o[8][4];
    #pragma unroll
    for (int nt = 0; nt < 8; nt++)
        #pragma unroll
        for (int c = 0; c < 4; c++) o[nt][c] = 0.f;
    float m0 = -1e30f, m1 = -1e30f, l0 = 0.f, l1 = 0.f;

    const int ntiles = 2 * qt + 2;
    ASTG(0, 0);

    for (int jt = 0; jt < ntiles; jt++) {
        asm volatile("cp.async.wait_group 0;");
        __syncthreads();
        if (jt + 1 < ntiles) {
            ASTG(jt + 1, (jt + 1) & 1);
        }

        const int kv0 = jt * 64;
        const uint32_t ksb = kvb0 + (uint32_t)(jt & 1) * ATTN_BUFB;
        const uint32_t vtb = ksb + ATTN_KVB;

        float s[8][4];
        #pragma unroll
        for (int nt = 0; nt < 8; nt++)
            #pragma unroll
            for (int c = 0; c < 4; c++) s[nt][c] = 0.f;

        #pragma unroll
        for (int ks = 0; ks < 4; ks++) {
            uint32_t a[4];
            ldsm_x4(a, qsb + (uint32_t)((wp * 16) * QS_HB + ks * 32) + lofQ);
            #pragma unroll
            for (int p = 0; p < 4; p++) {
                uint32_t bq[4];
                ldsm_x4(bq, ksb + (uint32_t)((p * 16) * QS_HB + ks * 32) + lofB);
                uint32_t b0[2] = {bq[0], bq[1]};
                uint32_t b1[2] = {bq[2], bq[3]};
                mma_f16(s[2 * p], a, b0);
                mma_f16(s[2 * p + 1], a, b1);
            }
        }

        if (jt >= 2 * qt) {
            int r0 = q0 + wp * 16 + g, r1 = r0 + 8;
            #pragma unroll
            for (int nt = 0; nt < 8; nt++) {
                int c0 = kv0 + nt * 8 + 2 * t;
                if (c0 > r0)     s[nt][0] = -1e30f;
                if (c0 + 1 > r0) s[nt][1] = -1e30f;
                if (c0 > r1)     s[nt][2] = -1e30f;
                if (c0 + 1 > r1) s[nt][3] = -1e30f;
            }
        }

        float mx0 = -1e30f, mx1 = -1e30f;
        #pragma unroll
        for (int nt = 0; nt < 8; nt++) {
            mx0 = fmaxf(mx0, fmaxf(s[nt][0], s[nt][1]));
            mx1 = fmaxf(mx1, fmaxf(s[nt][2], s[nt][3]));
        }
        mx0 = fmaxf(mx0, __shfl_xor_sync(0xffffffffu, mx0, 1));
        mx0 = fmaxf(mx0, __shfl_xor_sync(0xffffffffu, mx0, 2));
        mx1 = fmaxf(mx1, __shfl_xor_sync(0xffffffffu, mx1, 1));
        mx1 = fmaxf(mx1, __shfl_xor_sync(0xffffffffu, mx1, 2));
        float mn0 = fmaxf(m0, mx0), mn1 = fmaxf(m1, mx1);
        float corr0 = fexp2(m0 - mn0), corr1 = fexp2(m1 - mn1);
        m0 = mn0; m1 = mn1;
        float sum0 = 0.f, sum1 = 0.f;
        #pragma unroll
        for (int nt = 0; nt < 8; nt++) {
            s[nt][0] = fexp2(s[nt][0] - mn0);
            s[nt][1] = fexp2(s[nt][1] - mn0);
            s[nt][2] = fexp2(s[nt][2] - mn1);
            s[nt][3] = fexp2(s[nt][3] - mn1);
            sum0 += s[nt][0] + s[nt][1];
            sum1 += s[nt][2] + s[nt][3];
        }
        l0 = l0 * corr0 + sum0;
        l1 = l1 * corr1 + sum1;
        #pragma unroll
        for (int nt = 0; nt < 8; nt++) {
            o[nt][0] *= corr0; o[nt][1] *= corr0;
            o[nt][2] *= corr1; o[nt][3] *= corr1;
        }

        #pragma unroll
        for (int ks = 0; ks < 4; ks++) {
            uint32_t a[4];
            a[0] = pack_h2(s[2 * ks][0],     s[2 * ks][1]);
            a[1] = pack_h2(s[2 * ks][2],     s[2 * ks][3]);
            a[2] = pack_h2(s[2 * ks + 1][0], s[2 * ks + 1][1]);
            a[3] = pack_h2(s[2 * ks + 1][2], s[2 * ks + 1][3]);
            #pragma unroll
            for (int p = 0; p < 4; p++) {
                uint32_t bq[4];
                ldsm_x4(bq, vtb + (uint32_t)((p * 16) * QS_HB + ks * 32) + lofB);
                uint32_t b0[2] = {bq[0], bq[1]};
                uint32_t b1[2] = {bq[2], bq[3]};
                mma_f16(o[2 * p], a, b0);
                mma_f16(o[2 * p + 1], a, b1);
            }
        }
    }
    #undef ASTG

    l0 += __shfl_xor_sync(0xffffffffu, l0, 1);
    l0 += __shfl_xor_sync(0xffffffffu, l0, 2);
    l1 += __shfl_xor_sync(0xffffffffu, l1, 1);
    l1 += __shfl_xor_sync(0xffffffffu, l1, 2);
    float inv0 = 1.f / l0, inv1 = 1.f / l1;

    int b_ = bh >> 4, h = bh & (NH - 1);
    int r0 = q0 + wp * 16 + g, r1 = r0 + 8;
    __half* dst0 = g_aoh + ((size_t)b_ * SEQ + r0) * DIM + h * HD;
    __half* dst1 = g_aoh + ((size_t)b_ * SEQ + r1) * DIM + h * HD;
    #pragma unroll
    for (int nt = 0; nt < 8; nt++) {
        int cc = nt * 8 + 2 * t;
        *(__half2*)(dst0 + cc) = __floats2half2_rn(o[nt][0] * inv0, o[nt][1] * inv0);
        *(__half2*)(dst1 + cc) = __floats2half2_rn(o[nt][2] * inv1, o[nt][3] * inv1);
    }
}

// ---------------------------------------------------------------------------
extern "C" void kernel_launch(void* const* d_in, const int* in_sizes, int n_in,
                              void* d_out, int out_size) {
    const float* x     = (const float*)d_in[0];
    const float* W_qkv = (const float*)d_in[1];
    const float* b_qkv = (const float*)d_in[2];
    const float* W_out = (const float*)d_in[3];
    const float* b_out = (const float*)d_in[4];
    float* out = (float*)d_out;

    static __half* p_xh = nullptr;
    static __half* p_wqkvth = nullptr;
    static __half* p_woutth = nullptr;
    if (!p_xh) {
        cudaGetSymbolAddress((void**)&p_xh, g_xh);
        cudaGetSymbolAddress((void**)&p_wqkvth, g_wqkvth);
        cudaGetSymbolAddress((void**)&p_woutth, g_woutth);
        cudaFuncSetAttribute(attn_h, cudaFuncAttributeMaxDynamicSharedMemorySize, ATTN_SMEMH);
        cudaFuncSetAttribute(gemm_qkv_h, cudaFuncAttributeMaxDynamicSharedMemorySize, GEMM_SMEMH);
        cudaFuncSetAttribute(gemm_out_h, cudaFuncAttributeMaxDynamicSharedMemorySize, GEMM_SMEMH);
    }

    cvt_h_kernel<<<(MROWS*DIM/8 + 255)/256, 256>>>(x, p_xh, MROWS*DIM/8);
    cvt_t_h_kernel<<<dim3(QKV_N/32, DIM/32), dim3(32, 8)>>>(W_qkv, p_wqkvth, DIM, QKV_N);
    cvt_t_h_kernel<<<dim3(DIM/32, DIM/32), dim3(32, 8)>>>(W_out, p_woutth, DIM, DIM);

    gemm_qkv_h<<<dim3(QKV_N / 128, MROWS / 128), 256, GEMM_SMEMH>>>(b_qkv);
    attn_h<<<dim3(SEQ / 128, BATCH * NH), 256, ATTN_SMEMH>>>();
    gemm_out_h<<<dim3(DIM / 128, MROWS / 128), 256, GEMM_SMEMH>>>(b_out, out);
}

// round 15
// speedup vs baseline: 1.4257x; 1.4257x over previous
#include <cuda_runtime.h>
#include <cuda_fp16.h>
#include <cstdint>

// Problem constants
#define BATCH 2
#define SEQ   2048
#define DIM   1024
#define NH    16
#define HD    64
#define MROWS (BATCH*SEQ)          // 4096
#define QKV_N (3*DIM)              // 3072
#define QSC   0.18033688011112042f // 0.125 * log2(e); softmax uses ex2

// Scratch (device globals; no allocation allowed). All fp16.
__device__ __half g_xh[MROWS*DIM];        // x
__device__ __half g_wqkvth[QKV_N*DIM];    // W_qkv^T [n][k]
__device__ __half g_woutth[DIM*DIM];      // W_out^T [n][k]
__device__ __half g_qh[BATCH*NH*SEQ*HD];  // [b][h][s][d], scaled by QSC
__device__ __half g_kh[BATCH*NH*SEQ*HD];  // [b][h][s][d]
__device__ __half g_vth[BATCH*NH*HD*SEQ]; // [b][h][d][s]
__device__ __half g_aoh[BATCH*SEQ*DIM];   // attn out [b][s][h*64+d]

__device__ __forceinline__ void mma_f16(float (&d)[4],
                                        const uint32_t (&a)[4],
                                        const uint32_t (&b)[2]) {
    asm volatile(
        "mma.sync.aligned.m16n8k16.row.col.f32.f16.f16.f32 "
        "{%0,%1,%2,%3}, {%4,%5,%6,%7}, {%8,%9}, {%0,%1,%2,%3};"
        : "+f"(d[0]), "+f"(d[1]), "+f"(d[2]), "+f"(d[3])
        : "r"(a[0]), "r"(a[1]), "r"(a[2]), "r"(a[3]), "r"(b[0]), "r"(b[1]));
}

__device__ __forceinline__ void cp_async16(uint32_t smem, const void* gptr) {
    asm volatile("cp.async.cg.shared.global [%0], [%1], 16;" :: "r"(smem), "l"(gptr));
}

__device__ __forceinline__ uint32_t pack_h2(float x, float y) {
    __half2 h = __floats2half2_rn(x, y);
    return *reinterpret_cast<uint32_t*>(&h);
}

__device__ __forceinline__ float fexp2(float x) {
    float y;
    asm("ex2.approx.ftz.f32 %0, %1;" : "=f"(y) : "f"(x));
    return y;
}

__device__ __forceinline__ void ldsm_x4(uint32_t (&r)[4], uint32_t addr) {
    asm volatile(
        "ldmatrix.sync.aligned.m8n8.x4.shared.b16 {%0,%1,%2,%3}, [%4];"
        : "=r"(r[0]), "=r"(r[1]), "=r"(r[2]), "=r"(r[3]) : "r"(addr));
}

// ---------------------------------------------------------------------------
// Fused prep kernel: one launch converts x (copy) and both weights (transpose).
// 1D grid: [0,2048) x-copy blocks; [2048,5120) W_qkv tiles; [5120,6144) W_out.
// ---------------------------------------------------------------------------
#define XBLK 2048              // (MROWS*DIM/8)/256
#define WQKV_TILES (96*32)     // (QKV_N/32)*(DIM/32)
#define WOUT_TILES (32*32)

__global__ __launch_bounds__(256) void prep_kernel(const float* __restrict__ x,
                                                   const float* __restrict__ Wqkv,
                                                   const float* __restrict__ Wout) {
    const int b = blockIdx.x;
    const int tid = threadIdx.x;

    if (b < XBLK) {
        int i = b * 256 + tid;     // uint4 index (8 halves)
        float4 v0 = ((const float4*)x)[2 * i];
        float4 v1 = ((const float4*)x)[2 * i + 1];
        uint4 o;
        o.x = pack_h2(v0.x, v0.y);
        o.y = pack_h2(v0.z, v0.w);
        o.z = pack_h2(v1.x, v1.y);
        o.w = pack_h2(v1.z, v1.w);
        ((uint4*)g_xh)[i] = o;
        return;
    }

    __shared__ float tile[32][33];
    const int tx = tid & 31, ty = tid >> 5;   // (32, 8)

    const float* src;
    __half* dst;
    int N, nb, kb;
    if (b < XBLK + WQKV_TILES) {
        int tb = b - XBLK;
        N = QKV_N;
        nb = (tb % 96) * 32;
        kb = (tb / 96) * 32;
        src = Wqkv;
        dst = g_wqkvth;
    } else {
        int tb = b - XBLK - WQKV_TILES;
        N = DIM;
        nb = (tb % 32) * 32;
        kb = (tb / 32) * 32;
        src = Wout;
        dst = g_woutth;
    }

    #pragma unroll
    for (int i = 0; i < 32; i += 8)
        tile[ty + i][tx] = src[(size_t)(kb + ty + i) * N + nb + tx];
    __syncthreads();
    #pragma unroll
    for (int i = 0; i < 32; i += 8)
        dst[(size_t)(nb + ty + i) * DIM + kb + tx] = __float2half_rn(tile[tx][ty + i]);
}

// ---------------------------------------------------------------------------
// fp16 tensor-core GEMM: CTA 128x128, k-tile 64 halves (4 x k16 mma steps).
// 8 warps (2m x 4n). cp.async double buffer, one sync per k-tile. (R11 form.)
// ---------------------------------------------------------------------------
#define AS_HB 144u                     // bytes per smem row (72 halves)
#define GEMM_ABUF 18432u               // 128 rows * 144 B
#define GEMM_BUFB 36864u               // A + B per stage
#define GEMM_SMEMH (2 * 36864 + 256)

__device__ __forceinline__ void gemm_tile_h(const __half* __restrict__ Abase,
                                            const __half* __restrict__ Btbase,
                                            float (&acc)[4][4][4]) {
    extern __shared__ __half smh[];
    const int K = DIM;
    const int tid = threadIdx.x;
    const int lane = tid & 31;
    const int w = tid >> 5;
    const int warpM = (w & 1) * 64;
    const int warpN = (w >> 1) * 32;

    const __half* Ag  = Abase  + (size_t)(blockIdx.y * 128) * K;
    const __half* Bgt = Btbase + (size_t)(blockIdx.x * 128) * K;

    const int sub = lane >> 3, r8 = lane & 7;
    const uint32_t lofA = (uint32_t)(((sub & 1) * 8 + r8) * AS_HB + (sub >> 1) * 16);
    const uint32_t lofB = (uint32_t)(((sub >> 1) * 8 + r8) * AS_HB + (sub & 1) * 16);
    const uint32_t smb = (uint32_t)__cvta_generic_to_shared(smh);

    const int s_row = tid >> 3;        // 0..31 (+32 per it)
    const int s_c   = tid & 7;         // 16B chunk (8 halves)

#define HSTAGE(kt, buf) { \
    uint32_t ab = smb + (uint32_t)(buf) * GEMM_BUFB; \
    uint32_t bb = ab + GEMM_ABUF; \
    _Pragma("unroll") \
    for (int it = 0; it < 4; it++) { \
        int row = s_row + it * 32; \
        cp_async16(ab + (uint32_t)(row * AS_HB + s_c * 16), \
                   Ag + (size_t)row * K + (kt) * 64 + s_c * 8); \
        cp_async16(bb + (uint32_t)(row * AS_HB + s_c * 16), \
                   Bgt + (size_t)row * K + (kt) * 64 + s_c * 8); \
    } \
    asm volatile("cp.async.commit_group;"); }

    const int NKT = K / 64;   // 16
    HSTAGE(0, 0);
    for (int kt = 0; kt < NKT; kt++) {
        asm volatile("cp.async.wait_group 0;");
        __syncthreads();
        if (kt + 1 < NKT) HSTAGE(kt + 1, (kt + 1) & 1);

        const uint32_t ab = smb + (uint32_t)(kt & 1) * GEMM_BUFB;
        const uint32_t bb = ab + GEMM_ABUF;

        #pragma unroll
        for (int ks = 0; ks < 4; ks++) {
            uint32_t af[4][4];
            #pragma unroll
            for (int mt = 0; mt < 4; mt++)
                ldsm_x4(af[mt], ab + (uint32_t)((warpM + mt * 16) * AS_HB + ks * 32) + lofA);
            uint32_t bf[4][2];
            #pragma unroll
            for (int p = 0; p < 2; p++) {
                uint32_t bq[4];
                ldsm_x4(bq, bb + (uint32_t)((warpN + p * 16) * AS_HB + ks * 32) + lofB);
                bf[2 * p][0]     = bq[0];
                bf[2 * p][1]     = bq[1];
                bf[2 * p + 1][0] = bq[2];
                bf[2 * p + 1][1] = bq[3];
            }
            #pragma unroll
            for (int mt = 0; mt < 4; mt++)
                #pragma unroll
                for (int nt = 0; nt < 4; nt++)
                    mma_f16(acc[mt][nt], af[mt], bf[nt]);
        }
    }
#undef HSTAGE
}

__global__ __launch_bounds__(256) void gemm_qkv_h(const float* __restrict__ bias) {
    float acc[4][4][4];
    #pragma unroll
    for (int i = 0; i < 4; i++)
        #pragma unroll
        for (int j = 0; j < 4; j++)
            #pragma unroll
            for (int k = 0; k < 4; k++) acc[i][j][k] = 0.f;

    gemm_tile_h(g_xh, g_wqkvth, acc);

    const int tid = threadIdx.x;
    const int lane = tid & 31;
    const int w = tid >> 5;
    const int warpM = (w & 1) * 64;
    const int warpN = (w >> 1) * 32;
    const int g = lane >> 2, t = lane & 3;

    #pragma unroll
    for (int mt = 0; mt < 4; mt++) {
        #pragma unroll
        for (int nt = 0; nt < 4; nt++) {
            int col = blockIdx.x * 128 + warpN + nt * 8 + t * 2;
            float b0 = bias[col], b1 = bias[col + 1];
            int part = col >> 10;
            int h = (col >> 6) & (NH - 1);
            int d = col & (HD - 1);
            #pragma unroll
            for (int half = 0; half < 2; half++) {
                int r = blockIdx.y * 128 + warpM + mt * 16 + g + half * 8;
                int b_ = r >> 11, s = r & (SEQ - 1);
                float v0 = acc[mt][nt][half * 2 + 0] + b0;
                float v1 = acc[mt][nt][half * 2 + 1] + b1;
                if (part == 0) {
                    __half2* dst = (__half2*)(g_qh + ((size_t)(b_ * NH + h) * SEQ + s) * HD + d);
                    *dst = __floats2half2_rn(v0 * QSC, v1 * QSC);
                } else if (part == 1) {
                    __half2* dst = (__half2*)(g_kh + ((size_t)(b_ * NH + h) * SEQ + s) * HD + d);
                    *dst = __floats2half2_rn(v0, v1);
                } else {
                    size_t vb = ((size_t)(b_ * NH + h) * HD + d) * SEQ + s;
                    g_vth[vb]       = __float2half_rn(v0);
                    g_vth[vb + SEQ] = __float2half_rn(v1);
                }
            }
        }
    }
}

__global__ __launch_bounds__(256) void gemm_out_h(const float* __restrict__ bias,
                                                  float* __restrict__ C) {
    float acc[4][4][4];
    #pragma unroll
    for (int i = 0; i < 4; i++)
        #pragma unroll
        for (int j = 0; j < 4; j++)
            #pragma unroll
            for (int k = 0; k < 4; k++) acc[i][j][k] = 0.f;

    gemm_tile_h(g_aoh, g_woutth, acc);

    const int tid = threadIdx.x;
    const int lane = tid & 31;
    const int w = tid >> 5;
    const int warpM = (w & 1) * 64;
    const int warpN = (w >> 1) * 32;
    const int g = lane >> 2, t = lane & 3;

    #pragma unroll
    for (int mt = 0; mt < 4; mt++) {
        #pragma unroll
        for (int nt = 0; nt < 4; nt++) {
            int col = blockIdx.x * 128 + warpN + nt * 8 + t * 2;
            float b0 = bias[col], b1 = bias[col + 1];
            #pragma unroll
            for (int half = 0; half < 2; half++) {
                int r = blockIdx.y * 128 + warpM + mt * 16 + g + half * 8;
                float2 o;
                o.x = acc[mt][nt][half * 2 + 0] + b0;
                o.y = acc[mt][nt][half * 2 + 1] + b1;
                *(float2*)(C + (size_t)r * DIM + col) = o;
            }
        }
    }
}

// ---------------------------------------------------------------------------
// fp16 causal flash attention — R11 form (single 64-kv tile per barrier).
// ---------------------------------------------------------------------------
#define QS_HB 144u
#define ATTN_QBY (128 * 144)
#define ATTN_KVB (64 * 144)
#define ATTN_BUFB (2 * ATTN_KVB)
#define ATTN_SMEMH (ATTN_QBY + 2 * ATTN_BUFB)

__global__ __launch_bounds__(256, 2) void attn_h() {
    extern __shared__ __half smh[];

    const int tid = threadIdx.x;
    const int lane = tid & 31;
    const int wp = tid >> 5;
    const int g = lane >> 2, t = lane & 3;

    const int qt = (gridDim.x - 1) - blockIdx.x;
    const int bh = blockIdx.y;
    const int q0 = qt * 128;
    const __half* Qp  = g_qh  + (size_t)bh * SEQ * HD;
    const __half* Kp  = g_kh  + (size_t)bh * SEQ * HD;
    const __half* Vtp = g_vth + (size_t)bh * HD * SEQ;

    const int sub = lane >> 3, r8 = lane & 7;
    const uint32_t lofQ = (uint32_t)(((sub & 1) * 8 + r8) * QS_HB + (sub >> 1) * 16);
    const uint32_t lofB = (uint32_t)(((sub >> 1) * 8 + r8) * QS_HB + (sub & 1) * 16);
    const uint32_t qsb  = (uint32_t)__cvta_generic_to_shared(smh);
    const uint32_t kvb0 = qsb + ATTN_QBY;

    const int st_r = tid >> 3;
    const int st_c = tid & 7;

    #define ASTG(jt, buf) { \
        uint32_t ksb = kvb0 + (uint32_t)(buf) * ATTN_BUFB; \
        uint32_t vtb = ksb + ATTN_KVB; \
        int kv0_ = (jt) * 64; \
        _Pragma("unroll") \
        for (int it = 0; it < 2; it++) { \
            int r = st_r + it * 32; \
            cp_async16(ksb + (uint32_t)(r * QS_HB + st_c * 16), \
                       Kp + (size_t)(kv0_ + r) * HD + st_c * 8); \
            cp_async16(vtb + (uint32_t)(r * QS_HB + st_c * 16), \
                       Vtp + (size_t)r * SEQ + kv0_ + st_c * 8); \
        } \
        asm volatile("cp.async.commit_group;"); }

    for (int i = tid; i < 128 * 8; i += 256) {
        int r = i >> 3, c = i & 7;
        *(uint4*)((char*)smh + r * QS_HB + c * 16) =
            *(const uint4*)(Qp + (size_t)(q0 + r) * HD + c * 8);
    }

    float o[8][4];
    #pragma unroll
    for (int nt = 0; nt < 8; nt++)
        #pragma unroll
        for (int c = 0; c < 4; c++) o[nt][c] = 0.f;
    float m0 = -1e30f, m1 = -1e30f, l0 = 0.f, l1 = 0.f;

    const int ntiles = 2 * qt + 2;
    ASTG(0, 0);

    for (int jt = 0; jt < ntiles; jt++) {
        asm volatile("cp.async.wait_group 0;");
        __syncthreads();
        if (jt + 1 < ntiles) {
            ASTG(jt + 1, (jt + 1) & 1);
        }

        const int kv0 = jt * 64;
        const uint32_t ksb = kvb0 + (uint32_t)(jt & 1) * ATTN_BUFB;
        const uint32_t vtb = ksb + ATTN_KVB;

        float s[8][4];
        #pragma unroll
        for (int nt = 0; nt < 8; nt++)
            #pragma unroll
            for (int c = 0; c < 4; c++) s[nt][c] = 0.f;

        #pragma unroll
        for (int ks = 0; ks < 4; ks++) {
            uint32_t a[4];
            ldsm_x4(a, qsb + (uint32_t)((wp * 16) * QS_HB + ks * 32) + lofQ);
            #pragma unroll
            for (int p = 0; p < 4; p++) {
                uint32_t bq[4];
                ldsm_x4(bq, ksb + (uint32_t)((p * 16) * QS_HB + ks * 32) + lofB);
                uint32_t b0[2] = {bq[0], bq[1]};
                uint32_t b1[2] = {bq[2], bq[3]};
                mma_f16(s[2 * p], a, b0);
                mma_f16(s[2 * p + 1], a, b1);
            }
        }

        if (jt >= 2 * qt) {
            int r0 = q0 + wp * 16 + g, r1 = r0 + 8;
            #pragma unroll
            for (int nt = 0; nt < 8; nt++) {
                int c0 = kv0 + nt * 8 + 2 * t;
                if (c0 > r0)     s[nt][0] = -1e30f;
                if (c0 + 1 > r0) s[nt][1] = -1e30f;
                if (c0 > r1)     s[nt][2] = -1e30f;
                if (c0 + 1 > r1) s[nt][3] = -1e30f;
            }
        }

        float mx0 = -1e30f, mx1 = -1e30f;
        #pragma unroll
        for (int nt = 0; nt < 8; nt++) {
            mx0 = fmaxf(mx0, fmaxf(s[nt][0], s[nt][1]));
            mx1 = fmaxf(mx1, fmaxf(s[nt][2], s[nt][3]));
        }
        mx0 = fmaxf(mx0, __shfl_xor_sync(0xffffffffu, mx0, 1));
        mx0 = fmaxf(mx0, __shfl_xor_sync(0xffffffffu, mx0, 2));
        mx1 = fmaxf(mx1, __shfl_xor_sync(0xffffffffu, mx1, 1));
        mx1 = fmaxf(mx1, __shfl_xor_sync(0xffffffffu, mx1, 2));
        float mn0 = fmaxf(m0, mx0), mn1 = fmaxf(m1, mx1);
        float corr0 = fexp2(m0 - mn0), corr1 = fexp2(m1 - mn1);
        m0 = mn0; m1 = mn1;
        float sum0 = 0.f, sum1 = 0.f;
        #pragma unroll
        for (int nt = 0; nt < 8; nt++) {
            s[nt][0] = fexp2(s[nt][0] - mn0);
            s[nt][1] = fexp2(s[nt][1] - mn0);
            s[nt][2] = fexp2(s[nt][2] - mn1);
            s[nt][3] = fexp2(s[nt][3] - mn1);
            sum0 += s[nt][0] + s[nt][1];
            sum1 += s[nt][2] + s[nt][3];
        }
        l0 = l0 * corr0 + sum0;
        l1 = l1 * corr1 + sum1;
        #pragma unroll
        for (int nt = 0; nt < 8; nt++) {
            o[nt][0] *= corr0; o[nt][1] *= corr0;
            o[nt][2] *= corr1; o[nt][3] *= corr1;
        }

        #pragma unroll
        for (int ks = 0; ks < 4; ks++) {
            uint32_t a[4];
            a[0] = pack_h2(s[2 * ks][0],     s[2 * ks][1]);
            a[1] = pack_h2(s[2 * ks][2],     s[2 * ks][3]);
            a[2] = pack_h2(s[2 * ks + 1][0], s[2 * ks + 1][1]);
            a[3] = pack_h2(s[2 * ks + 1][2], s[2 * ks + 1][3]);
            #pragma unroll
            for (int p = 0; p < 4; p++) {
                uint32_t bq[4];
                ldsm_x4(bq, vtb + (uint32_t)((p * 16) * QS_HB + ks * 32) + lofB);
                uint32_t b0[2] = {bq[0], bq[1]};
                uint32_t b1[2] = {bq[2], bq[3]};
                mma_f16(o[2 * p], a, b0);
                mma_f16(o[2 * p + 1], a, b1);
            }
        }
    }
    #undef ASTG

    l0 += __shfl_xor_sync(0xffffffffu, l0, 1);
    l0 += __shfl_xor_sync(0xffffffffu, l0, 2);
    l1 += __shfl_xor_sync(0xffffffffu, l1, 1);
    l1 += __shfl_xor_sync(0xffffffffu, l1, 2);
    float inv0 = 1.f / l0, inv1 = 1.f / l1;

    int b_ = bh >> 4, h = bh & (NH - 1);
    int r0 = q0 + wp * 16 + g, r1 = r0 + 8;
    __half* dst0 = g_aoh + ((size_t)b_ * SEQ + r0) * DIM + h * HD;
    __half* dst1 = g_aoh + ((size_t)b_ * SEQ + r1) * DIM + h * HD;
    #pragma unroll
    for (int nt = 0; nt < 8; nt++) {
        int cc = nt * 8 + 2 * t;
        *(__half2*)(dst0 + cc) = __floats2half2_rn(o[nt][0] * inv0, o[nt][1] * inv0);
        *(__half2*)(dst1 + cc) = __floats2half2_rn(o[nt][2] * inv1, o[nt][3] * inv1);
    }
}

// ---------------------------------------------------------------------------
extern "C" void kernel_launch(void* const* d_in, const int* in_sizes, int n_in,
                              void* d_out, int out_size) {
    const float* x     = (const float*)d_in[0];
    const float* W_qkv = (const float*)d_in[1];
    const float* b_qkv = (const float*)d_in[2];
    const float* W_out = (const float*)d_in[3];
    const float* b_out = (const float*)d_in[4];
    float* out = (float*)d_out;

    static bool init = false;
    if (!init) {
        init = true;
        cudaFuncSetAttribute(attn_h, cudaFuncAttributeMaxDynamicSharedMemorySize, ATTN_SMEMH);
        cudaFuncSetAttribute(gemm_qkv_h, cudaFuncAttributeMaxDynamicSharedMemorySize, GEMM_SMEMH);
        cudaFuncSetAttribute(gemm_out_h, cudaFuncAttributeMaxDynamicSharedMemorySize, GEMM_SMEMH);
    }

    prep_kernel<<<XBLK + WQKV_TILES + WOUT_TILES, 256>>>(x, W_qkv, W_out);
    gemm_qkv_h<<<dim3(QKV_N / 128, MROWS / 128), 256, GEMM_SMEMH>>>(b_qkv);
    attn_h<<<dim3(SEQ / 128, BATCH * NH), 256, ATTN_SMEMH>>>();
    gemm_out_h<<<dim3(DIM / 128, MROWS / 128), 256, GEMM_SMEMH>>>(b_out, out);
}